// round 15
// baseline (speedup 1.0000x reference)
#include <cuda_runtime.h>
#include <stdint.h>

// out[e,f] = (node_src[src[e],f] + off_src[e,f]) * (node_tgt[tgt[e],f] + off_tgt[e,f])
// F = 256 floats, E = 300000, N = 50000, edge_ids int32. HBM-bound.
//
// R15: 4-phase range-phasing over BOTH gather operands.
// Proven (R14): a 25.6 MB gather slice stays L2-resident under the
// evict-first stream flood. Phases (blockIdx.y, executed ~in order):
//   y=0:(src<H,tgt<H) y=1:(src<H,tgt>=H) y=2:(src>=H,tgt<H) y=3:(src>=H,tgt>=H)
// so the src half persists across consecutive phase pairs. Per phase each
// gather WS = 25.6 MB; streams stay monotonic full-1KB-row order at 25%
// density. Streams/out use .cs evict-first. One warp = one edge row.

#define FEAT8 32      // 256 / 8
#define HALF  25000u  // N/2

struct F8 { float4 lo, hi; };

__device__ __forceinline__ F8 ldg_nc_32B(const void* p) {
    unsigned long long r0, r1, r2, r3;
    asm volatile("ld.global.nc.v4.b64 {%0,%1,%2,%3}, [%4];"
                 : "=l"(r0), "=l"(r1), "=l"(r2), "=l"(r3)
                 : "l"(p));
    F8 v;
    v.lo.x = __uint_as_float((unsigned)(r0));
    v.lo.y = __uint_as_float((unsigned)(r0 >> 32));
    v.lo.z = __uint_as_float((unsigned)(r1));
    v.lo.w = __uint_as_float((unsigned)(r1 >> 32));
    v.hi.x = __uint_as_float((unsigned)(r2));
    v.hi.y = __uint_as_float((unsigned)(r2 >> 32));
    v.hi.z = __uint_as_float((unsigned)(r3));
    v.hi.w = __uint_as_float((unsigned)(r3 >> 32));
    return v;
}

__global__ __launch_bounds__(256) void node_to_edge_kernel(
    const float* __restrict__ node_src,    // [N, 256]
    const float* __restrict__ node_tgt,    // [N, 256]
    const int* __restrict__ edge_src_ids,  // [E]
    const int* __restrict__ edge_tgt_ids,  // [E]
    const float4* __restrict__ off_src,    // [E, 64] as float4
    const float4* __restrict__ off_tgt,    // [E, 64]
    float4* __restrict__ out,              // [E, 64]
    unsigned E)
{
    unsigned tid = blockIdx.x * blockDim.x + threadIdx.x;
    unsigned e   = tid >> 5;        // edge id (warp id)
    if (e >= E) return;
    unsigned f8  = tid & 31;        // 8-float group within row

    unsigned s = (unsigned)__ldg(&edge_src_ids[e]);
    unsigned t = (unsigned)__ldg(&edge_tgt_ids[e]);

    // Phase filter (warp-uniform): y = (src_half << 1) | tgt_half
    unsigned phase = ((s >= HALF) << 1) | (t >= HALF);
    if (phase != blockIdx.y) return;

    // Single-use streams: evict-first, monotonic order within the phase.
    unsigned q = (e << 6) + f8 * 2;  // float4 index in edge row
    float4 b0 = __ldcs(&off_src[q]);
    float4 b1 = __ldcs(&off_src[q + 1]);
    float4 d0 = __ldcs(&off_tgt[q]);
    float4 d1 = __ldcs(&off_tgt[q + 1]);

    // Gathered node rows: 25.6 MB working set each per phase -> L2 hits.
    F8 a = ldg_nc_32B(node_src + (size_t)s * 256 + f8 * 8);
    F8 c = ldg_nc_32B(node_tgt + (size_t)t * 256 + f8 * 8);

    float4 r0, r1;
    r0.x = (a.lo.x + b0.x) * (c.lo.x + d0.x);
    r0.y = (a.lo.y + b0.y) * (c.lo.y + d0.y);
    r0.z = (a.lo.z + b0.z) * (c.lo.z + d0.z);
    r0.w = (a.lo.w + b0.w) * (c.lo.w + d0.w);
    r1.x = (a.hi.x + b1.x) * (c.hi.x + d1.x);
    r1.y = (a.hi.y + b1.y) * (c.hi.y + d1.y);
    r1.z = (a.hi.z + b1.z) * (c.hi.z + d1.z);
    r1.w = (a.hi.w + b1.w) * (c.hi.w + d1.w);

    __stcs(&out[q], r0);
    __stcs(&out[q + 1], r1);
}

extern "C" void kernel_launch(void* const* d_in, const int* in_sizes, int n_in,
                              void* d_out, int out_size) {
    // 0: node_src_feats [N,256] f32   1: node_tgt_feats [N,256] f32
    // 2: edge_ids [2,E] int32         3: off_edge_src [E,256] f32
    // 4: off_edge_tgt [E,256] f32
    const float*  node_src = (const float*)d_in[0];
    const float*  node_tgt = (const float*)d_in[1];
    const int*    edge_ids = (const int*)d_in[2];
    const float4* off_src  = (const float4*)d_in[3];
    const float4* off_tgt  = (const float4*)d_in[4];
    float4*       out      = (float4*)d_out;

    unsigned E = (unsigned)(in_sizes[2] / 2);
    const int* src_ids = edge_ids;
    const int* tgt_ids = edge_ids + E;

    // One warp per edge; 8 edges per 256-thread block; 4 phases in y.
    unsigned xblocks = (E * 32 + 255) / 256;
    dim3 grid(xblocks, 4, 1);

    node_to_edge_kernel<<<grid, 256>>>(
        node_src, node_tgt, src_ids, tgt_ids, off_src, off_tgt, out, E);
}

// round 16
// speedup vs baseline: 1.2018x; 1.2018x over previous
#include <cuda_runtime.h>
#include <stdint.h>

// out[e,f] = (node_src[src[e],f] + off_src[e,f]) * (node_tgt[tgt[e],f] + off_tgt[e,f])
// F = 256 floats, E = 300000, N = 50000, edge_ids int32. HBM-bound.
//
// FINAL FORM (measured optimum across 15 rounds):
//   - 8 floats/thread; one warp = one contiguous 1 KB edge row
//   - streams (off_src/off_tgt/out): 128-bit .cs evict-first, issued first
//   - node gathers: 256-bit nc loads (src with evict_last hint - measured
//     neutral, kept from the best-measured binary), tgt default
//   - 32-bit indexing
// Operating point: ~1.22 GB DRAM @ ~7.1 TB/s (89.5% of peak) = ~171.5 us.
// Rejected with measurements: evict_last pinning (no-op), .cv/.wt/.lu
// (regressions), edge sorting (stream-order destruction), feature/range
// phasing (byte savings < DRAM page-locality loss below 100% density).

#define FEAT8 32  // 256 / 8

struct F8 { float4 lo, hi; };

__device__ __forceinline__ F8 ldg_evict_last_32B(const void* p) {
    unsigned long long r0, r1, r2, r3;
    asm volatile("ld.global.nc.L2::evict_last.v4.b64 {%0,%1,%2,%3}, [%4];"
                 : "=l"(r0), "=l"(r1), "=l"(r2), "=l"(r3)
                 : "l"(p));
    F8 v;
    v.lo.x = __uint_as_float((unsigned)(r0));
    v.lo.y = __uint_as_float((unsigned)(r0 >> 32));
    v.lo.z = __uint_as_float((unsigned)(r1));
    v.lo.w = __uint_as_float((unsigned)(r1 >> 32));
    v.hi.x = __uint_as_float((unsigned)(r2));
    v.hi.y = __uint_as_float((unsigned)(r2 >> 32));
    v.hi.z = __uint_as_float((unsigned)(r3));
    v.hi.w = __uint_as_float((unsigned)(r3 >> 32));
    return v;
}

__device__ __forceinline__ F8 ldg_default_32B(const float* p) {
    const float4* p4 = (const float4*)p;
    F8 v;
    v.lo = __ldg(p4);
    v.hi = __ldg(p4 + 1);
    return v;
}

__global__ __launch_bounds__(256) void node_to_edge_kernel(
    const float* __restrict__ node_src,    // [N, 256]
    const float* __restrict__ node_tgt,    // [N, 256]
    const int* __restrict__ edge_src_ids,  // [E]
    const int* __restrict__ edge_tgt_ids,  // [E]
    const float4* __restrict__ off_src,    // [E, 64] as float4
    const float4* __restrict__ off_tgt,    // [E, 64]
    float4* __restrict__ out,              // [E, 64]
    unsigned total8)                       // E * 32
{
    unsigned idx = blockIdx.x * blockDim.x + threadIdx.x;
    if (idx >= total8) return;

    unsigned e  = idx >> 5;        // edge id
    unsigned f8 = idx & 31;        // 8-float group within row

    // Single-use streams first (DRAM-latency critical path), evict-first.
    unsigned q = idx * 2;          // float4 index
    float4 b0 = __ldcs(&off_src[q]);
    float4 b1 = __ldcs(&off_src[q + 1]);
    float4 d0 = __ldcs(&off_tgt[q]);
    float4 d1 = __ldcs(&off_tgt[q + 1]);

    unsigned s = (unsigned)__ldg(&edge_src_ids[e]);
    unsigned t = (unsigned)__ldg(&edge_tgt_ids[e]);

    // Gathered node rows: 32 B per table per thread.
    F8 a = ldg_evict_last_32B(node_src + (size_t)s * 256 + f8 * 8);
    F8 c = ldg_default_32B(node_tgt + (size_t)t * 256 + f8 * 8);

    float4 r0, r1;
    r0.x = (a.lo.x + b0.x) * (c.lo.x + d0.x);
    r0.y = (a.lo.y + b0.y) * (c.lo.y + d0.y);
    r0.z = (a.lo.z + b0.z) * (c.lo.z + d0.z);
    r0.w = (a.lo.w + b0.w) * (c.lo.w + d0.w);
    r1.x = (a.hi.x + b1.x) * (c.hi.x + d1.x);
    r1.y = (a.hi.y + b1.y) * (c.hi.y + d1.y);
    r1.z = (a.hi.z + b1.z) * (c.hi.z + d1.z);
    r1.w = (a.hi.w + b1.w) * (c.hi.w + d1.w);

    __stcs(&out[q], r0);
    __stcs(&out[q + 1], r1);
}

extern "C" void kernel_launch(void* const* d_in, const int* in_sizes, int n_in,
                              void* d_out, int out_size) {
    // 0: node_src_feats [N,256] f32   1: node_tgt_feats [N,256] f32
    // 2: edge_ids [2,E] int32         3: off_edge_src [E,256] f32
    // 4: off_edge_tgt [E,256] f32
    const float*  node_src = (const float*)d_in[0];
    const float*  node_tgt = (const float*)d_in[1];
    const int*    edge_ids = (const int*)d_in[2];
    const float4* off_src  = (const float4*)d_in[3];
    const float4* off_tgt  = (const float4*)d_in[4];
    float4*       out      = (float4*)d_out;

    unsigned E = (unsigned)(in_sizes[2] / 2);        // edge_ids has 2*E elems
    unsigned total8 = E * FEAT8;                     // 8-float groups of output

    const int* src_ids = edge_ids;                   // row 0
    const int* tgt_ids = edge_ids + E;               // row 1

    unsigned threads = 256;
    unsigned blocks = (total8 + threads - 1) / threads;
    node_to_edge_kernel<<<blocks, threads>>>(
        node_src, node_tgt, src_ids, tgt_ids, off_src, off_tgt, out, total8);
}

// round 17
// speedup vs baseline: 1.2049x; 1.0026x over previous
#include <cuda_runtime.h>
#include <stdint.h>

// out[e,f] = (node_src[src[e],f] + off_src[e,f]) * (node_tgt[tgt[e],f] + off_tgt[e,f])
// F = 256 floats, E = 300000, N = 50000, edge_ids int32. HBM-bound.
//
// FINAL FORM (measured optimum across 16 rounds; confirmed twice):
//   - 8 floats/thread; one warp = one contiguous 1 KB edge row
//   - streams (off_src/off_tgt/out): 128-bit .cs evict-first, issued first
//   - node gathers: 256-bit nc loads (src with evict_last hint — measured
//     neutral; kept from the best-measured binary), tgt default
//   - 32-bit indexing (regs=32, occ 82%)
// Operating point: 1.218 GB DRAM @ 7.10 TB/s (89.6% of peak) = 171.5 us
// kernel / 174.5 us total.
// Measured and rejected: evict_last pinning (no-op), .cv/.wt/.lu
// (regressions), edge sorting (destroys stream order), feature-slice and
// src/tgt-range phasing (byte savings < DRAM page-locality loss at any
// stream density below 100%).

#define FEAT8 32  // 256 / 8

struct F8 { float4 lo, hi; };

__device__ __forceinline__ F8 ldg_evict_last_32B(const void* p) {
    unsigned long long r0, r1, r2, r3;
    asm volatile("ld.global.nc.L2::evict_last.v4.b64 {%0,%1,%2,%3}, [%4];"
                 : "=l"(r0), "=l"(r1), "=l"(r2), "=l"(r3)
                 : "l"(p));
    F8 v;
    v.lo.x = __uint_as_float((unsigned)(r0));
    v.lo.y = __uint_as_float((unsigned)(r0 >> 32));
    v.lo.z = __uint_as_float((unsigned)(r1));
    v.lo.w = __uint_as_float((unsigned)(r1 >> 32));
    v.hi.x = __uint_as_float((unsigned)(r2));
    v.hi.y = __uint_as_float((unsigned)(r2 >> 32));
    v.hi.z = __uint_as_float((unsigned)(r3));
    v.hi.w = __uint_as_float((unsigned)(r3 >> 32));
    return v;
}

__device__ __forceinline__ F8 ldg_default_32B(const float* p) {
    const float4* p4 = (const float4*)p;
    F8 v;
    v.lo = __ldg(p4);
    v.hi = __ldg(p4 + 1);
    return v;
}

__global__ __launch_bounds__(256) void node_to_edge_kernel(
    const float* __restrict__ node_src,    // [N, 256]
    const float* __restrict__ node_tgt,    // [N, 256]
    const int* __restrict__ edge_src_ids,  // [E]
    const int* __restrict__ edge_tgt_ids,  // [E]
    const float4* __restrict__ off_src,    // [E, 64] as float4
    const float4* __restrict__ off_tgt,    // [E, 64]
    float4* __restrict__ out,              // [E, 64]
    unsigned total8)                       // E * 32
{
    unsigned idx = blockIdx.x * blockDim.x + threadIdx.x;
    if (idx >= total8) return;

    unsigned e  = idx >> 5;        // edge id
    unsigned f8 = idx & 31;        // 8-float group within row

    // Single-use streams first (DRAM-latency critical path), evict-first.
    unsigned q = idx * 2;          // float4 index
    float4 b0 = __ldcs(&off_src[q]);
    float4 b1 = __ldcs(&off_src[q + 1]);
    float4 d0 = __ldcs(&off_tgt[q]);
    float4 d1 = __ldcs(&off_tgt[q + 1]);

    unsigned s = (unsigned)__ldg(&edge_src_ids[e]);
    unsigned t = (unsigned)__ldg(&edge_tgt_ids[e]);

    // Gathered node rows: 32 B per table per thread.
    F8 a = ldg_evict_last_32B(node_src + (size_t)s * 256 + f8 * 8);
    F8 c = ldg_default_32B(node_tgt + (size_t)t * 256 + f8 * 8);

    float4 r0, r1;
    r0.x = (a.lo.x + b0.x) * (c.lo.x + d0.x);
    r0.y = (a.lo.y + b0.y) * (c.lo.y + d0.y);
    r0.z = (a.lo.z + b0.z) * (c.lo.z + d0.z);
    r0.w = (a.lo.w + b0.w) * (c.lo.w + d0.w);
    r1.x = (a.hi.x + b1.x) * (c.hi.x + d1.x);
    r1.y = (a.hi.y + b1.y) * (c.hi.y + d1.y);
    r1.z = (a.hi.z + b1.z) * (c.hi.z + d1.z);
    r1.w = (a.hi.w + b1.w) * (c.hi.w + d1.w);

    __stcs(&out[q], r0);
    __stcs(&out[q + 1], r1);
}

extern "C" void kernel_launch(void* const* d_in, const int* in_sizes, int n_in,
                              void* d_out, int out_size) {
    // 0: node_src_feats [N,256] f32   1: node_tgt_feats [N,256] f32
    // 2: edge_ids [2,E] int32         3: off_edge_src [E,256] f32
    // 4: off_edge_tgt [E,256] f32
    const float*  node_src = (const float*)d_in[0];
    const float*  node_tgt = (const float*)d_in[1];
    const int*    edge_ids = (const int*)d_in[2];
    const float4* off_src  = (const float4*)d_in[3];
    const float4* off_tgt  = (const float4*)d_in[4];
    float4*       out      = (float4*)d_out;

    unsigned E = (unsigned)(in_sizes[2] / 2);        // edge_ids has 2*E elems
    unsigned total8 = E * FEAT8;                     // 8-float groups of output

    const int* src_ids = edge_ids;                   // row 0
    const int* tgt_ids = edge_ids + E;               // row 1

    unsigned threads = 256;
    unsigned blocks = (total8 + threads - 1) / threads;
    node_to_edge_kernel<<<blocks, threads>>>(
        node_src, node_tgt, src_ids, tgt_ids, off_src, off_tgt, out, total8);
}